// round 9
// baseline (speedup 1.0000x reference)
#include <cuda_runtime.h>
#include <cuda_fp16.h>
#include <math.h>

// ---------------- problem constants ----------------
#define NCTA 148
#define NTHR 512
#define WPC  16                 // warps per CTA
#define NWRP (NCTA * WPC)       // 2368 warps grid-wide

#define Mm   10
#define Nn   10
#define TT   100
#define H1   1600
#define H2   400
#define HID  2000
#define DIN  30
#define DOUT 100

#define CHU  50                 // uint4 per row per chunk (= 400 halves)
#define HU4  (HID / 8)          // 250 uint4 per Wh row

// ---------------- global scratch (no allocation allowed) ----------------
__device__ float g_a[H1];
__device__ float g_h1[2][HID];
__device__ float g_h2[2][HID];
__device__ float g_g[H2];

// fp16 weight copies (converted every launch). ~93 MB, fits L2.
__device__ __half c_Wi0[3 * HID * H1];
__device__ __half c_Wh0[3 * HID * HID];
__device__ __half c_Wi1[3 * HID * HID];
__device__ __half c_Wh1[3 * HID * HID];
__device__ __half c_W2[H2 * HID];
__device__ __half c_W3[DOUT * H2];

// software grid barrier state
__device__ unsigned g_count;
__device__ volatile unsigned g_gen;

__device__ __forceinline__ void grid_sync() {
    __threadfence();
    __syncthreads();
    if (threadIdx.x == 0) {
        unsigned gen = g_gen;
        if (atomicAdd(&g_count, 1u) == (unsigned)gridDim.x - 1u) {
            g_count = 0u;
            __threadfence();
            g_gen = gen + 1u;
        } else {
            while (g_gen == gen) { __nanosleep(32); }
        }
        __threadfence();
    }
    __syncthreads();
}

__device__ __forceinline__ float wred(float v) {
    v += __shfl_xor_sync(0xffffffffu, v, 16);
    v += __shfl_xor_sync(0xffffffffu, v, 8);
    v += __shfl_xor_sync(0xffffffffu, v, 4);
    v += __shfl_xor_sync(0xffffffffu, v, 2);
    v += __shfl_xor_sync(0xffffffffu, v, 1);
    return v;
}

__device__ __forceinline__ float sigmoidf_(float x) {
    return 1.0f / (1.0f + expf(-x));
}

// dot of 8 fp16 weights (uint4) with 8 fp32 activations
__device__ __forceinline__ float dot8(uint4 w, float4 a, float4 b) {
    float2 p; float s;
    p = __half22float2(*(__half2*)&w.x); s  = p.x * a.x + p.y * a.y;
    p = __half22float2(*(__half2*)&w.y); s += p.x * a.z + p.y * a.w;
    p = __half22float2(*(__half2*)&w.z); s += p.x * b.x + p.y * b.y;
    p = __half22float2(*(__half2*)&w.w); s += p.x * b.z + p.y * b.w;
    return s;
}

__device__ __forceinline__ void cp16(unsigned saddr, const void* g) {
    asm volatile("cp.async.cg.shared.global [%0], [%1], 16;" :: "r"(saddr), "l"(g) : "memory");
}

// ---------------- fp32 -> fp16 conversion prologue ----------------
__device__ __forceinline__ void convert8(__half* dst, const float* src) {
    float4 a = *(const float4*)src;
    float4 b = *(const float4*)(src + 4);
    __half2 h0 = __floats2half2_rn(a.x, a.y);
    __half2 h1 = __floats2half2_rn(a.z, a.w);
    __half2 h2 = __floats2half2_rn(b.x, b.y);
    __half2 h3 = __floats2half2_rn(b.z, b.w);
    uint4 u;
    u.x = *(unsigned*)&h0; u.y = *(unsigned*)&h1;
    u.z = *(unsigned*)&h2; u.w = *(unsigned*)&h3;
    *(uint4*)dst = u;
}

__global__ void convert_k(const float* __restrict__ Wi0, const float* __restrict__ Wh0,
                          const float* __restrict__ Wi1, const float* __restrict__ Wh1,
                          const float* __restrict__ W2,  const float* __restrict__ W3) {
    size_t stride = (size_t)gridDim.x * blockDim.x * 8;
    for (size_t i = ((size_t)blockIdx.x * blockDim.x + threadIdx.x) * 8;
         i < (size_t)3 * HID * HID; i += stride) {
        convert8(c_Wh0 + i, Wh0 + i);
        convert8(c_Wi1 + i, Wi1 + i);
        convert8(c_Wh1 + i, Wh1 + i);
        if (i < (size_t)3 * HID * H1) convert8(c_Wi0 + i, Wi0 + i);
        if (i < (size_t)H2 * HID)     convert8(c_W2 + i, W2 + i);
        if (i < (size_t)DOUT * H2)    convert8(c_W3 + i, W3 + i);
    }
}

// Stream 3 weight rows (length nch*CHU uint4) through a double-buffered smem
// pipeline via cp.async; accumulate 3 dot products against smem activations.
__device__ __forceinline__ void stream3(
    const uint4* __restrict__ r0, const uint4* __restrict__ r1,
    const uint4* __restrict__ r2,
    const float4* __restrict__ act,     // smem activations (float4)
    int nch,
    const uint4* __restrict__ buf, unsigned buf_u32, int lane,
    float& A0, float& A1, float& A2)
{
    // prefetch chunk 0 -> buffer 0
    for (int idx = lane; idx < 3 * CHU; idx += 32) {
        int row = idx / CHU, col = idx - row * CHU;
        const uint4* src = (row == 0 ? r0 : (row == 1 ? r1 : r2)) + col;
        cp16(buf_u32 + (unsigned)idx * 16u, src);
    }
    asm volatile("cp.async.commit_group;" ::: "memory");

    for (int c = 0; c < nch; c++) {
        if (c + 1 < nch) {
            int boff = ((c + 1) & 1) * (3 * CHU);
            for (int idx = lane; idx < 3 * CHU; idx += 32) {
                int row = idx / CHU, col = idx - row * CHU;
                const uint4* src = (row == 0 ? r0 : (row == 1 ? r1 : r2)) + (c + 1) * CHU + col;
                cp16(buf_u32 + (unsigned)(boff + idx) * 16u, src);
            }
            asm volatile("cp.async.commit_group;" ::: "memory");
            asm volatile("cp.async.wait_group 1;" ::: "memory");
        } else {
            asm volatile("cp.async.wait_group 0;" ::: "memory");
        }
        __syncwarp();
        const uint4* bf = buf + (c & 1) * (3 * CHU);
        {
            int col = lane;
            float4 xa = act[(c * CHU + col) * 2], xb = act[(c * CHU + col) * 2 + 1];
            A0 += dot8(bf[col],           xa, xb);
            A1 += dot8(bf[CHU + col],     xa, xb);
            A2 += dot8(bf[2 * CHU + col], xa, xb);
        }
        if (lane < CHU - 32) {
            int col = lane + 32;
            float4 xa = act[(c * CHU + col) * 2], xb = act[(c * CHU + col) * 2 + 1];
            A0 += dot8(bf[col],           xa, xb);
            A1 += dot8(bf[CHU + col],     xa, xb);
            A2 += dot8(bf[2 * CHU + col], xa, xb);
        }
        __syncwarp();   // all lanes done reading before next prefetch overwrites
    }
}

// One GRU layer. KXU4 = Wi row length in uint4 (200 for cell0, 250 for cell1).
template<int KXU4>
__device__ __forceinline__ void gru_phase_cp(
    const __half* __restrict__ Wi, const __half* __restrict__ Wh,
    const float* __restrict__ bi, const float* __restrict__ bh,
    const float* __restrict__ xg,      // input activations, KXU4*8 floats (global)
    const float* __restrict__ hg,      // previous hidden, HID floats (global)
    float* __restrict__ hnew,
    float* s_x, float* s_h, const uint4* mybuf, unsigned mybuf_u32,
    int tid, int gwarp, int lane)
{
    // CTA-wide stage of activations into smem
    {
        const float4* xs = (const float4*)xg;
        const float4* hs = (const float4*)hg;
        float4* sx4 = (float4*)s_x;
        float4* sh4 = (float4*)s_h;
        for (int i = tid; i < KXU4 * 2; i += NTHR) sx4[i] = xs[i];
        for (int i = tid; i < HID / 4; i += NTHR)  sh4[i] = hs[i];
    }
    __syncthreads();

    int j = gwarp;
    if (j < HID) {
        const uint4* wi = (const uint4*)Wi;
        const uint4* wh = (const uint4*)Wh;
        float ai0 = 0.f, ai1 = 0.f, ai2 = 0.f;
        float ah0 = 0.f, ah1 = 0.f, ah2 = 0.f;
        stream3(wi + (size_t)j * KXU4, wi + ((size_t)j + HID) * KXU4,
                wi + ((size_t)j + 2 * HID) * KXU4,
                (const float4*)s_x, KXU4 / CHU, mybuf, mybuf_u32, lane, ai0, ai1, ai2);
        stream3(wh + (size_t)j * HU4, wh + ((size_t)j + HID) * HU4,
                wh + ((size_t)j + 2 * HID) * HU4,
                (const float4*)s_h, HU4 / CHU, mybuf, mybuf_u32, lane, ah0, ah1, ah2);

        float rs = wred(ai0 + ah0);
        float zs = wred(ai1 + ah1);
        float ni = wred(ai2);
        float nh = wred(ah2);
        if (lane == 0) {
            float rr = sigmoidf_(rs + bi[j]         + bh[j]);
            float zz = sigmoidf_(zs + bi[j + HID]   + bh[j + HID]);
            float nn = tanhf    (ni + bi[j + 2*HID] + rr * (nh + bh[j + 2*HID]));
            hnew[j] = (1.0f - zz) * nn + zz * s_h[j];
        }
    }
}

__global__ void __launch_bounds__(NTHR, 1) knet_kernel(
    const float* __restrict__ y,    const float* __restrict__ m1x_0,
    const float* __restrict__ F,    const float* __restrict__ Hm,
    const float* __restrict__ h0,
    const float* __restrict__ W1,   const float* __restrict__ b1,
    const float* __restrict__ bi0,  const float* __restrict__ bh0,
    const float* __restrict__ bi1,  const float* __restrict__ bh1,
    const float* __restrict__ b2,   const float* __restrict__ b3,
    float* __restrict__ out)
{
    __shared__ float s_post[Mm], s_prevpost[Mm], s_prevprior[Mm], s_yprev[Nn];
    __shared__ float s_prior[Mm], s_dy[Nn], s_np[Mm];
    __shared__ float s_diff[32], s_inv[4], s_kin[32];
    __shared__ float s_KG[DOUT];
    __shared__ __align__(16) float s_g[H2];
    // dynamic smem: [0, 8000) s_x; [8000, 16000) s_h; then 16 warps x 300 uint4
    extern __shared__ __align__(16) char dynsmem[];
    float* s_x = (float*)dynsmem;                  // 2000 floats max
    float* s_h = (float*)(dynsmem + 8000);         // 2000 floats
    uint4* bufs = (uint4*)(dynsmem + 16000);       // 16 * 2 * 150 uint4

    const int tid   = threadIdx.x;
    const int lane  = tid & 31;
    const int warp  = tid >> 5;
    const int gwarp = blockIdx.x * WPC + warp;
    const int gtid  = blockIdx.x * NTHR + tid;

    const uint4* mybuf = bufs + warp * (2 * 3 * CHU);
    const unsigned mybuf_u32 = (unsigned)__cvta_generic_to_shared(mybuf);

    // ------------- init -------------
    for (int i = gtid; i < HID; i += NCTA * NTHR) {
        g_h1[0][i] = h0[i];
        g_h2[0][i] = h0[HID + i];
    }
    if (tid < Mm) {
        float v = m1x_0[tid];
        s_post[tid] = v; s_prevpost[tid] = 0.0f; s_prevprior[tid] = v;
    }
    __syncthreads();
    if (tid < Mm) {   // tmp = F @ m1x_0
        float pr = 0.f;
        #pragma unroll
        for (int j = 0; j < Mm; j++) pr += F[tid * Mm + j] * s_post[j];
        s_prior[tid] = pr;
    }
    __syncthreads();
    if (tid < Nn) {   // y_prev0 = Hm @ tmp
        float v = 0.f;
        #pragma unroll
        for (int j = 0; j < Mm; j++) v += Hm[tid * Mm + j] * s_prior[j];
        s_yprev[tid] = v;
    }
    grid_sync();

    // ------------- time loop -------------
    for (int t = 0; t <= TT; t++) {
        if (t > 0) {
            // finalize prev step: KG = W3 @ g + b3 (W3 fp16 from L2), post update
            for (int i = tid; i < H2; i += NTHR) s_g[i] = g_g[i];
            __syncthreads();
            {
                const float4* g4 = (const float4*)s_g;
                for (int r = warp; r < DOUT; r += WPC) {
                    const uint4* w = (const uint4*)c_W3 + r * (H2 / 8);
                    float acc = dot8(w[lane], g4[lane * 2], g4[lane * 2 + 1]);
                    if (lane < (H2 / 8) - 32) {
                        int c2 = lane + 32;
                        acc += dot8(w[c2], g4[c2 * 2], g4[c2 * 2 + 1]);
                    }
                    acc = wred(acc);
                    if (lane == 0) s_KG[r] = acc + b3[r];
                }
            }
            __syncthreads();
            if (tid < Mm) {
                float np = s_prior[tid];
                #pragma unroll
                for (int j = 0; j < Nn; j++) np += s_KG[tid * Nn + j] * s_dy[j];
                s_np[tid] = np;
                if (blockIdx.x == 0) out[tid * TT + (t - 1)] = np;
            }
            __syncthreads();
            if (tid < Mm) {
                s_prevpost[tid]  = s_post[tid];
                s_prevprior[tid] = s_prior[tid];
                s_post[tid]      = s_np[tid];
                s_yprev[tid]     = y[tid * TT + (t - 1)];
            }
            __syncthreads();
        }
        if (t == TT) break;
        const int p = t & 1;

        // -------- phase A: prior, dy, features, a = relu(W1@kin + b1) --------
        if (tid < Mm) {
            float pr = 0.f;
            #pragma unroll
            for (int j = 0; j < Mm; j++) pr += F[tid * Mm + j] * s_post[j];
            s_prior[tid] = pr;
        }
        __syncthreads();
        if (tid < Nn) {
            float my = 0.f;
            #pragma unroll
            for (int j = 0; j < Mm; j++) my += Hm[tid * Mm + j] * s_prior[j];
            float yt = y[tid * TT + t];
            s_dy[tid]   = yt - my;
            s_diff[tid] = yt - s_yprev[tid];
        }
        if (tid < Mm) {
            s_diff[10 + tid] = s_post[tid] - s_prevpost[tid];
            s_diff[20 + tid] = s_post[tid] - s_prevprior[tid];
        }
        __syncthreads();
        if (tid < 3) {
            float ss = 0.f;
            #pragma unroll
            for (int j = 0; j < 10; j++) { float d = s_diff[tid * 10 + j]; ss += d * d; }
            s_inv[tid] = 1.0f / fmaxf(sqrtf(ss), 1e-12f);
        }
        __syncthreads();
        if (tid < DIN) s_kin[tid] = s_diff[tid] * s_inv[tid / 10];
        __syncthreads();
        for (int r = gwarp; r < H1; r += NWRP) {
            float acc = (lane < DIN) ? W1[r * DIN + lane] * s_kin[lane] : 0.f;
            acc = wred(acc);
            if (lane == 0) g_a[r] = fmaxf(acc + b1[r], 0.0f);
        }
        grid_sync();

        // -------- phase B: GRU cell 0 --------
        gru_phase_cp<H1 / 8>(c_Wi0, c_Wh0, bi0, bh0, g_a, g_h1[p], g_h1[p ^ 1],
                             s_x, s_h, mybuf, mybuf_u32, tid, gwarp, lane);
        grid_sync();

        // -------- phase C: GRU cell 1 --------
        gru_phase_cp<HID / 8>(c_Wi1, c_Wh1, bi1, bh1, g_h1[p ^ 1], g_h2[p], g_h2[p ^ 1],
                              s_x, s_h, mybuf, mybuf_u32, tid, gwarp, lane);
        grid_sync();

        // -------- phase D: g = relu(W2 @ h2n + b2) --------
        {
            const float4* h4 = (const float4*)(g_h2[p ^ 1]);
            for (int r = gwarp; r < H2; r += NWRP) {
                const uint4* w4 = (const uint4*)(c_W2 + (size_t)r * HID);
                float acc = 0.f;
                #pragma unroll 2
                for (int k = lane; k < HID / 8; k += 32) {
                    uint4 w = w4[k];
                    acc += dot8(w, h4[2 * k], h4[2 * k + 1]);
                }
                acc = wred(acc);
                if (lane == 0) g_g[r] = fmaxf(acc + b2[r], 0.0f);
            }
        }
        grid_sync();
    }
}

extern "C" void kernel_launch(void* const* d_in, const int* in_sizes, int n_in,
                              void* d_out, int out_size) {
    const float* y     = (const float*)d_in[0];
    const float* m1x_0 = (const float*)d_in[1];
    const float* F     = (const float*)d_in[2];
    const float* Hm    = (const float*)d_in[3];
    const float* h0    = (const float*)d_in[4];
    const float* W1    = (const float*)d_in[5];
    const float* b1    = (const float*)d_in[6];
    const float* Wi0   = (const float*)d_in[7];
    const float* Wh0   = (const float*)d_in[8];
    const float* bi0   = (const float*)d_in[9];
    const float* bh0   = (const float*)d_in[10];
    const float* Wi1   = (const float*)d_in[11];
    const float* Wh1   = (const float*)d_in[12];
    const float* bi1   = (const float*)d_in[13];
    const float* bh1   = (const float*)d_in[14];
    const float* W2    = (const float*)d_in[15];
    const float* b2    = (const float*)d_in[16];
    const float* W3    = (const float*)d_in[17];
    const float* b3    = (const float*)d_in[18];
    float* out = (float*)d_out;

    // prologue: fp32 -> fp16 weight conversion (graph-capturable, deterministic)
    convert_k<<<4096, 512>>>(Wi0, Wh0, Wi1, Wh1, W2, W3);

    // dynamic smem: 16000 B activations + 16 warps * 300 uint4 * 16 B = 92800 B
    const size_t shmem = 16000 + (size_t)WPC * 2 * 3 * CHU * 16;
    cudaFuncSetAttribute(knet_kernel,
                         cudaFuncAttributeMaxDynamicSharedMemorySize, (int)shmem);
    knet_kernel<<<NCTA, NTHR, shmem>>>(
        y, m1x_0, F, Hm, h0, W1, b1, bi0, bh0,
        bi1, bh1, b2, b3, out);
}

// round 13
// speedup vs baseline: 1.2415x; 1.2415x over previous
#include <cuda_runtime.h>
#include <cuda_fp16.h>
#include <math.h>

// ---------------- problem constants ----------------
#define NCTA 148
#define NTHR 512
#define WPC  16                 // warps per CTA
#define NWRP (NCTA * WPC)       // 2368 warps grid-wide

#define Mm   10
#define Nn   10
#define TT   100
#define H1   1600
#define H2   400
#define HID  2000
#define DIN  30
#define DOUT 100

// ---------------- global scratch (no allocation allowed) ----------------
__device__ float g_a[H1];
__device__ float g_h1[2][HID];
__device__ float g_h2[2][HID];
__device__ float g_g[H2];

// fp16 weight copies (converted every launch). ~93 MB, fits L2.
__device__ __half c_Wi0[3 * HID * H1];
__device__ __half c_Wh0[3 * HID * HID];
__device__ __half c_Wi1[3 * HID * HID];
__device__ __half c_Wh1[3 * HID * HID];
__device__ __half c_W2[H2 * HID];

// software grid barrier state
__device__ unsigned g_count;
__device__ volatile unsigned g_gen;

__device__ __forceinline__ void grid_sync() {
    __threadfence();
    __syncthreads();
    if (threadIdx.x == 0) {
        unsigned gen = g_gen;
        if (atomicAdd(&g_count, 1u) == (unsigned)gridDim.x - 1u) {
            g_count = 0u;
            __threadfence();
            g_gen = gen + 1u;
        } else {
            while (g_gen == gen) { __nanosleep(32); }
        }
        __threadfence();
    }
    __syncthreads();
}

__device__ __forceinline__ float wred(float v) {
    v += __shfl_xor_sync(0xffffffffu, v, 16);
    v += __shfl_xor_sync(0xffffffffu, v, 8);
    v += __shfl_xor_sync(0xffffffffu, v, 4);
    v += __shfl_xor_sync(0xffffffffu, v, 2);
    v += __shfl_xor_sync(0xffffffffu, v, 1);
    return v;
}

__device__ __forceinline__ float sigmoidf_(float x) {
    return 1.0f / (1.0f + expf(-x));
}

// dot of 8 fp16 weights (uint4) with 8 fp32 activations
__device__ __forceinline__ float dot8(uint4 w, float4 a, float4 b) {
    float2 p; float s;
    p = __half22float2(*(__half2*)&w.x); s  = p.x * a.x + p.y * a.y;
    p = __half22float2(*(__half2*)&w.y); s += p.x * a.z + p.y * a.w;
    p = __half22float2(*(__half2*)&w.z); s += p.x * b.x + p.y * b.y;
    p = __half22float2(*(__half2*)&w.w); s += p.x * b.z + p.y * b.w;
    return s;
}

// ---------------- fp32 -> fp16 conversion prologue ----------------
__device__ __forceinline__ void convert8(__half* dst, const float* src) {
    float4 a = *(const float4*)src;
    float4 b = *(const float4*)(src + 4);
    __half2 h0 = __floats2half2_rn(a.x, a.y);
    __half2 h1 = __floats2half2_rn(a.z, a.w);
    __half2 h2 = __floats2half2_rn(b.x, b.y);
    __half2 h3 = __floats2half2_rn(b.z, b.w);
    uint4 u;
    u.x = *(unsigned*)&h0; u.y = *(unsigned*)&h1;
    u.z = *(unsigned*)&h2; u.w = *(unsigned*)&h3;
    *(uint4*)dst = u;
}

__global__ void convert_k(const float* __restrict__ Wi0, const float* __restrict__ Wh0,
                          const float* __restrict__ Wi1, const float* __restrict__ Wh1,
                          const float* __restrict__ W2) {
    size_t stride = (size_t)gridDim.x * blockDim.x * 8;
    for (size_t i = ((size_t)blockIdx.x * blockDim.x + threadIdx.x) * 8;
         i < (size_t)3 * HID * HID; i += stride) {
        convert8(c_Wh0 + i, Wh0 + i);
        convert8(c_Wi1 + i, Wi1 + i);
        convert8(c_Wh1 + i, Wh1 + i);
        if (i < (size_t)3 * HID * H1) convert8(c_Wi0 + i, Wi0 + i);
        if (i < (size_t)H2 * HID)     convert8(c_W2 + i, W2 + i);
    }
}

// One GRU layer: warp-per-hidden-unit, fp16 weights streamed from L2 into
// registers; ACTIVATIONS READ FROM SMEM (staged once per phase) so the whole
// register budget goes to in-flight weight loads.
// KXU = Wi row length in uint4 (200 for cell0, 250 for cell1). HU = 250.
template<int KXU>
__device__ __forceinline__ void gru_phase_s(
    const __half* __restrict__ Wi, const __half* __restrict__ Wh,
    const float* __restrict__ bi, const float* __restrict__ bh,
    const float* __restrict__ xg,      // input acts (global), KXU*8 floats
    const float* __restrict__ hg,      // prev hidden (global), HID floats
    float* __restrict__ hnew,
    float* s_x, float* s_h,
    int tid, int gwarp, int lane)
{
    constexpr int KX = KXU * 8;
    constexpr int HU = HID / 8;        // 250
    // CTA-wide stage of activations into smem
    {
        const float4* xs = (const float4*)xg;
        const float4* hs = (const float4*)hg;
        float4* sx4 = (float4*)s_x;
        float4* sh4 = (float4*)s_h;
        for (int i = tid; i < KXU * 2; i += NTHR) sx4[i] = xs[i];
        for (int i = tid; i < HID / 4; i += NTHR) sh4[i] = hs[i];
    }
    __syncthreads();

    const float4* sx4 = (const float4*)s_x;
    const float4* sh4 = (const float4*)s_h;
    int j = gwarp;                     // NWRP (2368) >= HID (2000): one unit max
    if (j < HID) {
        const uint4* wir = (const uint4*)(Wi + (size_t)j * KX);
        const uint4* wiz = (const uint4*)(Wi + ((size_t)j + HID) * KX);
        const uint4* win = (const uint4*)(Wi + ((size_t)j + 2 * HID) * KX);
        const uint4* whr = (const uint4*)(Wh + (size_t)j * HID);
        const uint4* whz = (const uint4*)(Wh + ((size_t)j + HID) * HID);
        const uint4* whn = (const uint4*)(Wh + ((size_t)j + 2 * HID) * HID);

        float air = 0.f, aiz = 0.f, ain = 0.f;
        float ahr = 0.f, ahz = 0.f, ahn = 0.f;
        #pragma unroll 2
        for (int k = lane; k < KXU; k += 32) {
            uint4 w0 = wir[k], w1 = wiz[k], w2 = win[k];
            uint4 v0 = whr[k], v1 = whz[k], v2 = whn[k];
            float4 xa = sx4[2 * k], xb = sx4[2 * k + 1];
            float4 ha = sh4[2 * k], hb = sh4[2 * k + 1];
            air += dot8(w0, xa, xb);
            aiz += dot8(w1, xa, xb);
            ain += dot8(w2, xa, xb);
            ahr += dot8(v0, ha, hb);
            ahz += dot8(v1, ha, hb);
            ahn += dot8(v2, ha, hb);
        }
        if constexpr (KXU < HU) {
            #pragma unroll 2
            for (int k = KXU + lane; k < HU; k += 32) {
                uint4 v0 = whr[k], v1 = whz[k], v2 = whn[k];
                float4 ha = sh4[2 * k], hb = sh4[2 * k + 1];
                ahr += dot8(v0, ha, hb);
                ahz += dot8(v1, ha, hb);
                ahn += dot8(v2, ha, hb);
            }
        }
        float rs = wred(air + ahr);
        float zs = wred(aiz + ahz);
        float ni = wred(ain);
        float nh = wred(ahn);
        if (lane == 0) {
            float rr = sigmoidf_(rs + bi[j]         + bh[j]);
            float zz = sigmoidf_(zs + bi[j + HID]   + bh[j + HID]);
            float nn = tanhf    (ni + bi[j + 2*HID] + rr * (nh + bh[j + 2*HID]));
            hnew[j] = (1.0f - zz) * nn + zz * s_h[j];
        }
    }
}

__global__ void __launch_bounds__(NTHR, 1) knet_kernel(
    const float* __restrict__ y,    const float* __restrict__ m1x_0,
    const float* __restrict__ F,    const float* __restrict__ Hm,
    const float* __restrict__ h0,
    const float* __restrict__ W1,   const float* __restrict__ b1,
    const float* __restrict__ bi0,  const float* __restrict__ bh0,
    const float* __restrict__ bi1,  const float* __restrict__ bh1,
    const float* __restrict__ b2,
    const float* __restrict__ W3,   const float* __restrict__ b3,
    float* __restrict__ out)
{
    __shared__ float s_post[Mm], s_prevpost[Mm], s_prevprior[Mm], s_yprev[Nn];
    __shared__ float s_prior[Mm], s_dy[Nn], s_np[Mm];
    __shared__ float s_diff[32], s_inv[4], s_kin[32];
    __shared__ float s_KG[DOUT];
    __shared__ float s_g[H2];
    // dynamic smem: W3s (160000 B) | s_x (8000 B) | s_h (8000 B)
    extern __shared__ __align__(16) char dynsmem[];
    float* W3s = (float*)dynsmem;
    float* s_x = (float*)(dynsmem + 160000);
    float* s_h = (float*)(dynsmem + 168000);

    const int tid   = threadIdx.x;
    const int lane  = tid & 31;
    const int warp  = tid >> 5;
    const int gwarp = blockIdx.x * WPC + warp;
    const int gtid  = blockIdx.x * NTHR + tid;

    // ------------- init -------------
    for (int i = gtid; i < HID; i += NCTA * NTHR) {
        g_h1[0][i] = h0[i];
        g_h2[0][i] = h0[HID + i];
    }
    for (int i = tid; i < DOUT * H2; i += NTHR) W3s[i] = W3[i];
    if (tid < Mm) {
        float v = m1x_0[tid];
        s_post[tid] = v; s_prevpost[tid] = 0.0f; s_prevprior[tid] = v;
    }
    __syncthreads();
    if (tid < Mm) {   // tmp = F @ m1x_0
        float pr = 0.f;
        #pragma unroll
        for (int j = 0; j < Mm; j++) pr += F[tid * Mm + j] * s_post[j];
        s_prior[tid] = pr;
    }
    __syncthreads();
    if (tid < Nn) {   // y_prev0 = Hm @ tmp
        float v = 0.f;
        #pragma unroll
        for (int j = 0; j < Mm; j++) v += Hm[tid * Mm + j] * s_prior[j];
        s_yprev[tid] = v;
    }
    grid_sync();

    // ------------- time loop -------------
    for (int t = 0; t <= TT; t++) {
        if (t > 0) {
            // finalize prev step: KG = W3 @ g + b3, new_post = prior + KG @ dy
            for (int i = tid; i < H2; i += NTHR) s_g[i] = g_g[i];
            __syncthreads();
            for (int r = warp; r < DOUT; r += WPC) {
                float acc = 0.f;
                for (int k = lane; k < H2; k += 32) acc += W3s[r * H2 + k] * s_g[k];
                acc = wred(acc);
                if (lane == 0) s_KG[r] = acc + b3[r];
            }
            __syncthreads();
            if (tid < Mm) {
                float np = s_prior[tid];
                #pragma unroll
                for (int j = 0; j < Nn; j++) np += s_KG[tid * Nn + j] * s_dy[j];
                s_np[tid] = np;
                if (blockIdx.x == 0) out[tid * TT + (t - 1)] = np;
            }
            __syncthreads();
            if (tid < Mm) {
                s_prevpost[tid]  = s_post[tid];
                s_prevprior[tid] = s_prior[tid];
                s_post[tid]      = s_np[tid];
                s_yprev[tid]     = y[tid * TT + (t - 1)];
            }
            __syncthreads();
        }
        if (t == TT) break;
        const int p = t & 1;

        // -------- phase A: prior, dy, features, a = relu(W1@kin + b1) --------
        if (tid < Mm) {
            float pr = 0.f;
            #pragma unroll
            for (int j = 0; j < Mm; j++) pr += F[tid * Mm + j] * s_post[j];
            s_prior[tid] = pr;
        }
        __syncthreads();
        if (tid < Nn) {
            float my = 0.f;
            #pragma unroll
            for (int j = 0; j < Mm; j++) my += Hm[tid * Mm + j] * s_prior[j];
            float yt = y[tid * TT + t];
            s_dy[tid]   = yt - my;
            s_diff[tid] = yt - s_yprev[tid];
        }
        if (tid < Mm) {
            s_diff[10 + tid] = s_post[tid] - s_prevpost[tid];
            s_diff[20 + tid] = s_post[tid] - s_prevprior[tid];
        }
        __syncthreads();
        if (tid < 3) {
            float ss = 0.f;
            #pragma unroll
            for (int j = 0; j < 10; j++) { float d = s_diff[tid * 10 + j]; ss += d * d; }
            s_inv[tid] = 1.0f / fmaxf(sqrtf(ss), 1e-12f);
        }
        __syncthreads();
        if (tid < DIN) s_kin[tid] = s_diff[tid] * s_inv[tid / 10];
        __syncthreads();
        for (int r = gwarp; r < H1; r += NWRP) {
            float acc = (lane < DIN) ? W1[r * DIN + lane] * s_kin[lane] : 0.f;
            acc = wred(acc);
            if (lane == 0) g_a[r] = fmaxf(acc + b1[r], 0.0f);
        }
        grid_sync();

        // -------- phase B: GRU cell 0 (KXU = 200) --------
        gru_phase_s<H1 / 8>(c_Wi0, c_Wh0, bi0, bh0, g_a, g_h1[p], g_h1[p ^ 1],
                            s_x, s_h, tid, gwarp, lane);
        grid_sync();

        // -------- phase C: GRU cell 1 (KXU = 250) --------
        gru_phase_s<HID / 8>(c_Wi1, c_Wh1, bi1, bh1, g_h1[p ^ 1], g_h2[p], g_h2[p ^ 1],
                             s_x, s_h, tid, gwarp, lane);
        grid_sync();

        // -------- phase D: g = relu(W2 @ h2n + b2), acts staged in smem --------
        {
            const float4* hs = (const float4*)(g_h2[p ^ 1]);
            float4* sx4 = (float4*)s_x;
            for (int i = tid; i < HID / 4; i += NTHR) sx4[i] = hs[i];
            __syncthreads();
            const float4* h4 = (const float4*)s_x;
            for (int r = gwarp; r < H2; r += NWRP) {
                const uint4* w4 = (const uint4*)(c_W2 + (size_t)r * HID);
                float acc = 0.f;
                #pragma unroll 2
                for (int k = lane; k < HID / 8; k += 32) {
                    uint4 w = w4[k];
                    acc += dot8(w, h4[2 * k], h4[2 * k + 1]);
                }
                acc = wred(acc);
                if (lane == 0) g_g[r] = fmaxf(acc + b2[r], 0.0f);
            }
        }
        grid_sync();
    }
}

extern "C" void kernel_launch(void* const* d_in, const int* in_sizes, int n_in,
                              void* d_out, int out_size) {
    const float* y     = (const float*)d_in[0];
    const float* m1x_0 = (const float*)d_in[1];
    const float* F     = (const float*)d_in[2];
    const float* Hm    = (const float*)d_in[3];
    const float* h0    = (const float*)d_in[4];
    const float* W1    = (const float*)d_in[5];
    const float* b1    = (const float*)d_in[6];
    const float* Wi0   = (const float*)d_in[7];
    const float* Wh0   = (const float*)d_in[8];
    const float* bi0   = (const float*)d_in[9];
    const float* bh0   = (const float*)d_in[10];
    const float* bi1   = (const float*)d_in[13];
    const float* Wi1   = (const float*)d_in[11];
    const float* Wh1   = (const float*)d_in[12];
    const float* bh1   = (const float*)d_in[14];
    const float* W2    = (const float*)d_in[15];
    const float* b2    = (const float*)d_in[16];
    const float* W3    = (const float*)d_in[17];
    const float* b3    = (const float*)d_in[18];
    float* out = (float*)d_out;

    // prologue: fp32 -> fp16 weight conversion (graph-capturable, deterministic)
    convert_k<<<4096, 512>>>(Wi0, Wh0, Wi1, Wh1, W2);

    // dynamic smem: 160000 (W3s fp32) + 8000 (s_x) + 8000 (s_h) = 176000 B
    const size_t shmem = 176000;
    cudaFuncSetAttribute(knet_kernel,
                         cudaFuncAttributeMaxDynamicSharedMemorySize, (int)shmem);
    knet_kernel<<<NCTA, NTHR, shmem>>>(
        y, m1x_0, F, Hm, h0, W1, b1, bi0, bh0,
        bi1, bh1, b2, W3, b3, out);
}